// round 3
// baseline (speedup 1.0000x reference)
#include <cuda_runtime.h>
#include <cstdint>
#include <cstddef>

// ---------------------------------------------------------------------------
// ProteinAWDLSTM: 3-layer LSTM with token resets.
//   T=512, B=32, D_IN=512, H_HID=1280
// Per layer: px = x @ wi^T + bi  (one fp32 GEMM, M=16384)
//            ONE persistent scan kernel (128 CTAs, grid barrier per step).
// Graph nodes total: 1 + 3*(1+1+1) + 2 = 12  (fixes 6 MB graph-upload residue)
// ---------------------------------------------------------------------------

#define T_LEN 512
#define BATCH 32
#define DIN   512
#define HHID  1280

// -------------------- device scratch (no allocs allowed) -------------------
__device__ float g_px [16384 * 5120];        // px for current layer
__device__ float g_y0 [16384 * 1280];        // layer0 out / layer1 in
__device__ float g_y1 [16384 * 1280];        // layer1 out / layer2 in
__device__ float g_hA [BATCH * HHID];        // h ping
__device__ float g_hB [BATCH * HHID];        // h pong
__device__ float g_c  [BATCH * HHID];
__device__ unsigned char g_rm[T_LEN * BATCH];
__device__ unsigned int  g_bar;

// ------------------------------- setup -------------------------------------
__global__ __launch_bounds__(256) void setup_rm(const int* __restrict__ tok,
                                                unsigned char* __restrict__ rm) {
    int idx = blockIdx.x * 256 + threadIdx.x;      // < 16384
    int t = idx >> 5, b = idx & 31;
    rm[idx] = (t >= 2 && tok[(t - 1) * 32 + b] == 0) ? 1 : 0;
}

__global__ __launch_bounds__(256) void init_layer(float* __restrict__ hA,
                                                  float* __restrict__ hB,
                                                  float* __restrict__ c,
                                                  unsigned int* __restrict__ bar,
                                                  int n) {
    int i = blockIdx.x * 256 + threadIdx.x;
    if (i < n) { hA[i] = 0.f; hB[i] = 0.f; c[i] = 0.f; }
    if (i == 0) *bar = 0u;
}

// --------------------------- input-projection GEMM -------------------------
// C[16384, N] = A[16384, K] @ B[N, K]^T + bias[N]; 128x128x8 tiles.
__global__ __launch_bounds__(256) void gemm_bias(
    const float* __restrict__ A, const float* __restrict__ B,
    const float* __restrict__ bias, float* __restrict__ C,
    int N, int K)
{
    __shared__ float As[8][128];
    __shared__ float Bs[8][128];

    const int bm = blockIdx.y, bn = blockIdx.x;
    const int tid  = threadIdx.x;
    const int lrow = tid >> 1;
    const int lkv  = tid & 1;

    const float* Ap = A + (size_t)(bm * 128 + lrow) * K + lkv * 4;
    const float* Bp = B + (size_t)(bn * 128 + lrow) * K + lkv * 4;

    const int warp = tid >> 5, lane = tid & 31;
    const int wm = warp & 3, wn = warp >> 2;
    const int lm = lane & 3, ln = lane >> 2;
    const int tm0 = wm * 32 + lm * 8;
    const int tn0 = wn * 64 + ln * 8;

    float acc[8][8];
    #pragma unroll
    for (int i = 0; i < 8; i++)
        #pragma unroll
        for (int j = 0; j < 8; j++) acc[i][j] = 0.f;

    float4 av = *(const float4*)(Ap);
    float4 bv = *(const float4*)(Bp);

    for (int k0 = 0; k0 < K; k0 += 8) {
        __syncthreads();
        As[lkv * 4 + 0][lrow] = av.x; As[lkv * 4 + 1][lrow] = av.y;
        As[lkv * 4 + 2][lrow] = av.z; As[lkv * 4 + 3][lrow] = av.w;
        Bs[lkv * 4 + 0][lrow] = bv.x; Bs[lkv * 4 + 1][lrow] = bv.y;
        Bs[lkv * 4 + 2][lrow] = bv.z; Bs[lkv * 4 + 3][lrow] = bv.w;
        __syncthreads();
        if (k0 + 8 < K) {
            av = *(const float4*)(Ap + k0 + 8);
            bv = *(const float4*)(Bp + k0 + 8);
        }
        #pragma unroll
        for (int k = 0; k < 8; k++) {
            float ar[8], br[8];
            *(float4*)&ar[0] = *(const float4*)&As[k][tm0];
            *(float4*)&ar[4] = *(const float4*)&As[k][tm0 + 4];
            *(float4*)&br[0] = *(const float4*)&Bs[k][tn0];
            *(float4*)&br[4] = *(const float4*)&Bs[k][tn0 + 4];
            #pragma unroll
            for (int i = 0; i < 8; i++)
                #pragma unroll
                for (int j = 0; j < 8; j++)
                    acc[i][j] = fmaf(ar[i], br[j], acc[i][j]);
        }
    }

    float bv8[8];
    #pragma unroll
    for (int j = 0; j < 8; j++) bv8[j] = bias[bn * 128 + tn0 + j];

    #pragma unroll
    for (int i = 0; i < 8; i++) {
        size_t row = (size_t)(bm * 128 + tm0 + i);
        float* Cp = &C[row * N + bn * 128 + tn0];
        float4 o0, o1;
        o0.x = acc[i][0] + bv8[0]; o0.y = acc[i][1] + bv8[1];
        o0.z = acc[i][2] + bv8[2]; o0.w = acc[i][3] + bv8[3];
        o1.x = acc[i][4] + bv8[4]; o1.y = acc[i][5] + bv8[5];
        o1.z = acc[i][6] + bv8[6]; o1.w = acc[i][7] + bv8[7];
        *(float4*)&Cp[0] = o0;
        *(float4*)&Cp[4] = o1;
    }
}

// --------------------- persistent LSTM scan (one per layer) ----------------
// Grid = 128 CTAs x 256 threads. CTA owns JR hidden columns (all 4 gates,
// all 32 batches, full K). Threads: kq(4 K-quarters) x rg(8 row groups) x
// bq(8 batch quads). SMEM reduce over kq, then in-CTA pointwise epilogue.
// One grid barrier per timestep; h double-buffered across steps.
template <int H, int JR>
__global__ __launch_bounds__(256) void lstm_scan(
    const float* __restrict__ px,     // [T*32, 4H]
    const float* __restrict__ wh,     // [4H, H]
    const float* __restrict__ bh,     // [4H]
    const unsigned char* __restrict__ rm,
    float* __restrict__ hA, float* __restrict__ hB,
    float* __restrict__ c,
    float* __restrict__ y,            // [T*32, H]
    unsigned int* __restrict__ bar)
{
    constexpr int ROWS = 4 * JR;          // gate rows per CTA
    constexpr int TMr  = ROWS / 8;        // rows per thread
    constexpr int KC   = H / 4;           // K chunk per kq
    constexpr int NT   = KC / 32;         // 32-wide k tiles per kq
    constexpr int G    = 4 * H;
    constexpr int WSTR = ROWS + 1;        // padded row stride for ws
    constexpr int NW4  = ROWS * 8 / 64;   // w float4s per thread per tile
    static_assert(ROWS % 8 == 0 && KC % 32 == 0, "tiling");

    __shared__ __align__(16) float hs[4][32][36];              // [kq][k][b]
    constexpr int WS_FLOATS = 4 * 32 * WSTR;
    constexpr int PS_FLOATS = 4 * ROWS * 32;
    __shared__ __align__(16) float wsps[(WS_FLOATS > PS_FLOATS) ? WS_FLOATS
                                                                : PS_FLOATS];

    const int tid = threadIdx.x;
    const int kq  = tid >> 6;             // 0..3
    const int f   = tid & 63;             // lane within kq group
    const int rg  = (tid >> 3) & 7;       // 0..7
    const int bq  = tid & 7;              // 0..7
    const int r0  = rg * TMr;
    const int b0  = bq * 4;
    const int j0  = blockIdx.x * JR;
    const unsigned ncta = gridDim.x;

    for (int t = 0; t < T_LEN; t++) {
        const float* hin  = (t & 1) ? hB : hA;
        float*       hout = (t & 1) ? hA : hB;

        // ---- prefetch tile 0 into registers ----
        float4 wv[NW4], hv[4];
        {
            const int kbase = kq * KC;
            #pragma unroll
            for (int i = 0; i < NW4; i++) {
                int flat = f + i * 64, lr = flat >> 3, k4 = flat & 7;
                int grow = (lr / JR) * H + j0 + (lr % JR);
                wv[i] = *(const float4*)&wh[(size_t)grow * H + kbase + k4 * 4];
            }
            #pragma unroll
            for (int i = 0; i < 4; i++) {
                int flat = f + i * 64, b = flat >> 3, k4 = flat & 7;
                float4 v = __ldcg((const float4*)&hin[(size_t)b * H + kbase + k4 * 4]);
                if (rm[t * 32 + b]) { v.x = 0.f; v.y = 0.f; v.z = 0.f; v.w = 0.f; }
                hv[i] = v;
            }
        }

        float acc[TMr][4];
        #pragma unroll
        for (int i = 0; i < TMr; i++)
            #pragma unroll
            for (int j = 0; j < 4; j++) acc[i][j] = 0.f;

        for (int tile = 0; tile < NT; tile++) {
            __syncthreads();              // prev compute / epilogue done
            #pragma unroll
            for (int i = 0; i < NW4; i++) {
                int flat = f + i * 64, lr = flat >> 3, k4 = flat & 7;
                float* w = &wsps[kq * (32 * WSTR) + (k4 * 4) * WSTR + lr];
                w[0 * WSTR] = wv[i].x; w[1 * WSTR] = wv[i].y;
                w[2 * WSTR] = wv[i].z; w[3 * WSTR] = wv[i].w;
            }
            #pragma unroll
            for (int i = 0; i < 4; i++) {
                int flat = f + i * 64, b = flat >> 3, k4 = flat & 7;
                hs[kq][k4 * 4 + 0][b] = hv[i].x;
                hs[kq][k4 * 4 + 1][b] = hv[i].y;
                hs[kq][k4 * 4 + 2][b] = hv[i].z;
                hs[kq][k4 * 4 + 3][b] = hv[i].w;
            }
            __syncthreads();

            if (tile + 1 < NT) {          // prefetch next tile
                const int k0 = kq * KC + (tile + 1) * 32;
                #pragma unroll
                for (int i = 0; i < NW4; i++) {
                    int flat = f + i * 64, lr = flat >> 3, k4 = flat & 7;
                    int grow = (lr / JR) * H + j0 + (lr % JR);
                    wv[i] = *(const float4*)&wh[(size_t)grow * H + k0 + k4 * 4];
                }
                #pragma unroll
                for (int i = 0; i < 4; i++) {
                    int flat = f + i * 64, b = flat >> 3, k4 = flat & 7;
                    float4 v = __ldcg((const float4*)&hin[(size_t)b * H + k0 + k4 * 4]);
                    if (rm[t * 32 + b]) { v.x = 0.f; v.y = 0.f; v.z = 0.f; v.w = 0.f; }
                    hv[i] = v;
                }
            }

            #pragma unroll
            for (int kk = 0; kk < 32; kk++) {
                float4 hh = *(const float4*)&hs[kq][kk][b0];
                float wr[TMr];
                #pragma unroll
                for (int i = 0; i < TMr; i++)
                    wr[i] = wsps[kq * (32 * WSTR) + kk * WSTR + r0 + i];
                #pragma unroll
                for (int i = 0; i < TMr; i++) {
                    acc[i][0] = fmaf(wr[i], hh.x, acc[i][0]);
                    acc[i][1] = fmaf(wr[i], hh.y, acc[i][1]);
                    acc[i][2] = fmaf(wr[i], hh.z, acc[i][2]);
                    acc[i][3] = fmaf(wr[i], hh.w, acc[i][3]);
                }
            }
        }

        __syncthreads();                  // ws no longer needed -> reuse as ps
        #pragma unroll
        for (int i = 0; i < TMr; i++)
            #pragma unroll
            for (int j = 0; j < 4; j++)
                wsps[kq * (ROWS * 32) + (r0 + i) * 32 + b0 + j] = acc[i][j];
        __syncthreads();

        // ---- pointwise epilogue: this CTA's JR columns x 32 batches ----
        for (int e = tid; e < JR * 32; e += 256) {
            int jj = e >> 5, b = e & 31;
            int j = j0 + jj;
            float pre[4];
            #pragma unroll
            for (int g = 0; g < 4; g++) {
                int r = g * JR + jj;
                float s = bh[g * H + j]
                        + px[(size_t)(t * 32 + b) * G + g * H + j];
                #pragma unroll
                for (int q = 0; q < 4; q++)
                    s += wsps[q * (ROWS * 32) + r * 32 + b];
                pre[g] = s;
            }
            float ig = 1.f / (1.f + expf(-pre[0]));
            float fg = 1.f / (1.f + expf(-pre[1]));
            float og = 1.f / (1.f + expf(-pre[2]));
            float gg = tanhf(pre[3]);
            float cold = rm[t * 32 + b] ? 0.f : c[(size_t)b * H + j];
            float cn = fg * cold + ig * gg;
            float hn = og * tanhf(cn);
            c[(size_t)b * H + j]    = cn;
            hout[(size_t)b * H + j] = hn;
            y[(size_t)(t * 32 + b) * H + j] = hn;
        }

        // ---- grid barrier (h/c/y visible before next step's reads) ----
        if (t + 1 < T_LEN) {
            __threadfence();
            __syncthreads();
            if (tid == 0) {
                atomicAdd(bar, 1u);
                unsigned target = (unsigned)(t + 1) * ncta;
                while (*(volatile unsigned int*)bar < target) { }
            }
            __syncthreads();
        }
    }
}

// ------------------------------- launch -------------------------------------
extern "C" void kernel_launch(void* const* d_in, const int* in_sizes, int n_in,
                              void* d_out, int out_size)
{
    (void)in_sizes; (void)n_in; (void)out_size;
    const float* x   = (const float*)d_in[0];
    const int*   tok = (const int*)d_in[1];
    const float* wi[3] = {(const float*)d_in[2], (const float*)d_in[6],  (const float*)d_in[10]};
    const float* bi[3] = {(const float*)d_in[3], (const float*)d_in[7],  (const float*)d_in[11]};
    const float* wh[3] = {(const float*)d_in[4], (const float*)d_in[8],  (const float*)d_in[12]};
    const float* bh[3] = {(const float*)d_in[5], (const float*)d_in[9],  (const float*)d_in[13]};
    float* out = (float*)d_out;

    float *px = nullptr, *y0 = nullptr, *y1 = nullptr, *hA = nullptr,
          *hB = nullptr, *cb = nullptr;
    unsigned char* rmp = nullptr;
    unsigned int* bar = nullptr;
    cudaGetSymbolAddress((void**)&px,  g_px);
    cudaGetSymbolAddress((void**)&y0,  g_y0);
    cudaGetSymbolAddress((void**)&y1,  g_y1);
    cudaGetSymbolAddress((void**)&hA,  g_hA);
    cudaGetSymbolAddress((void**)&hB,  g_hB);
    cudaGetSymbolAddress((void**)&cb,  g_c);
    cudaGetSymbolAddress((void**)&rmp, g_rm);
    cudaGetSymbolAddress((void**)&bar, g_bar);

    setup_rm<<<64, 256>>>(tok, rmp);

    const float* lin[3] = {x, y0, y1};
    float*       lys[3] = {y0, y1, out};
    const int Hs[3] = {HHID, HHID, DIN};
    const int Ks[3] = {DIN, HHID, HHID};

    for (int l = 0; l < 3; l++) {
        const int H = Hs[l], G = 4 * H, K = Ks[l];
        const int n = BATCH * H;
        init_layer<<<(n + 255) / 256, 256>>>(hA, hB, cb, bar, n);

        gemm_bias<<<dim3(G / 128, 16384 / 128), 256>>>(lin[l], wi[l], bi[l], px, G, K);

        if (l < 2) {
            lstm_scan<HHID, 10><<<128, 256>>>(px, wh[l], bh[l], rmp,
                                              hA, hB, cb, lys[l], bar);
        } else {
            lstm_scan<DIN, 4><<<128, 256>>>(px, wh[l], bh[l], rmp,
                                            hA, hB, cb, lys[l], bar);
        }
    }

    // T_LEN even -> final h lives in hA; append h_last, c_last after y2
    cudaMemcpyAsync(out + 8388608,         hA, BATCH * DIN * sizeof(float),
                    cudaMemcpyDeviceToDevice);
    cudaMemcpyAsync(out + 8388608 + 16384, cb, BATCH * DIN * sizeof(float),
                    cudaMemcpyDeviceToDevice);
}

// round 5
// speedup vs baseline: 1.0753x; 1.0753x over previous
#include <cuda_runtime.h>
#include <cuda_bf16.h>
#include <cstdint>
#include <cstddef>

// ---------------------------------------------------------------------------
// ProteinAWDLSTM: 3-layer LSTM with token resets.
//   T=512, B=32, D_IN=512, H_HID=1280
// Per layer:
//   1) split inputs/weights into bf16 hi+lo
//   2) px = x @ wi^T + bi  via mma.sync bf16 GEMM (3-pass hi/lo, fp32 acc)
//      (baseline PTX only: harness targets plain sm_103, no tcgen05)
//   3) persistent fp32 scan kernel (128 CTAs, grid barrier per step)
// ---------------------------------------------------------------------------

#define T_LEN 512
#define BATCH 32
#define DIN   512
#define HHID  1280

// -------------------- device scratch (no allocs allowed) -------------------
__device__ float g_px [16384 * 5120];        // px for current layer
__device__ float g_y0 [16384 * 1280];        // layer0 out / layer1 in
__device__ float g_y1 [16384 * 1280];        // layer1 out / layer2 in
__device__ float g_hA [BATCH * HHID];
__device__ float g_hB [BATCH * HHID];
__device__ float g_c  [BATCH * HHID];
__device__ unsigned char g_rm[T_LEN * BATCH];
__device__ unsigned int  g_bar;
__device__ __nv_bfloat16 g_ahi[16384 * 1280];
__device__ __nv_bfloat16 g_alo[16384 * 1280];
__device__ __nv_bfloat16 g_bhi[5120 * 1280];
__device__ __nv_bfloat16 g_blo[5120 * 1280];

// --------------------------- PTX helpers (baseline) -------------------------
__device__ __forceinline__ uint32_t smem_u32(const void* p) {
    uint32_t a;
    asm("{ .reg .u64 t; cvta.to.shared.u64 t, %1; cvt.u32.u64 %0, t; }"
        : "=r"(a) : "l"(p));
    return a;
}
__device__ __forceinline__ void cp_async16(uint32_t dst, const void* src) {
    asm volatile("cp.async.cg.shared.global [%0], [%1], 16;"
                 :: "r"(dst), "l"(src) : "memory");
}
__device__ __forceinline__ void cp_commit() {
    asm volatile("cp.async.commit_group;" ::: "memory");
}
__device__ __forceinline__ void cp_wait1() {
    asm volatile("cp.async.wait_group 1;" ::: "memory");
}
__device__ __forceinline__ void ldmx4(uint32_t* r, uint32_t addr) {
    asm volatile("ldmatrix.sync.aligned.m8n8.x4.shared.b16 {%0,%1,%2,%3}, [%4];"
                 : "=r"(r[0]), "=r"(r[1]), "=r"(r[2]), "=r"(r[3]) : "r"(addr));
}
__device__ __forceinline__ void mma16816(float* c, const uint32_t* a,
                                         const uint32_t* b) {
    asm volatile("mma.sync.aligned.m16n8k16.row.col.f32.bf16.bf16.f32 "
                 "{%0,%1,%2,%3}, {%4,%5,%6,%7}, {%8,%9}, {%0,%1,%2,%3};"
                 : "+f"(c[0]), "+f"(c[1]), "+f"(c[2]), "+f"(c[3])
                 : "r"(a[0]), "r"(a[1]), "r"(a[2]), "r"(a[3]),
                   "r"(b[0]), "r"(b[1]));
}

// ------------------------------- setup -------------------------------------
__global__ __launch_bounds__(256) void setup_rm(const int* __restrict__ tok,
                                                unsigned char* __restrict__ rm) {
    int idx = blockIdx.x * 256 + threadIdx.x;      // < 16384
    int t = idx >> 5, b = idx & 31;
    rm[idx] = (t >= 2 && tok[(t - 1) * 32 + b] == 0) ? 1 : 0;
}

__global__ __launch_bounds__(256) void init_layer(float* __restrict__ hA,
                                                  float* __restrict__ hB,
                                                  float* __restrict__ c,
                                                  unsigned int* __restrict__ bar,
                                                  int n) {
    int i = blockIdx.x * 256 + threadIdx.x;
    if (i < n) { hA[i] = 0.f; hB[i] = 0.f; c[i] = 0.f; }
    if (i == 0) *bar = 0u;
}

// ------------------------- fp32 -> bf16 hi/lo split --------------------------
__global__ __launch_bounds__(256) void cvt_split(const float* __restrict__ x,
                                                 __nv_bfloat16* __restrict__ hi,
                                                 __nv_bfloat16* __restrict__ lo,
                                                 int n4) {
    int i = blockIdx.x * 256 + threadIdx.x;
    if (i >= n4) return;
    float4 v = ((const float4*)x)[i];
    __nv_bfloat16 h0 = __float2bfloat16(v.x);
    __nv_bfloat16 h1 = __float2bfloat16(v.y);
    __nv_bfloat16 h2 = __float2bfloat16(v.z);
    __nv_bfloat16 h3 = __float2bfloat16(v.w);
    __nv_bfloat16 l0 = __float2bfloat16(v.x - __bfloat162float(h0));
    __nv_bfloat16 l1 = __float2bfloat16(v.y - __bfloat162float(h1));
    __nv_bfloat16 l2 = __float2bfloat16(v.z - __bfloat162float(h2));
    __nv_bfloat16 l3 = __float2bfloat16(v.w - __bfloat162float(h3));
    ((__nv_bfloat162*)hi)[2 * i]     = __nv_bfloat162(h0, h1);
    ((__nv_bfloat162*)hi)[2 * i + 1] = __nv_bfloat162(h2, h3);
    ((__nv_bfloat162*)lo)[2 * i]     = __nv_bfloat162(l0, l1);
    ((__nv_bfloat162*)lo)[2 * i + 1] = __nv_bfloat162(l2, l3);
}

// ----------------------- mma.sync bf16 split GEMM ----------------------------
// C[M,N] = A[M,K] @ B[N,K]^T + bias, via hi*hi + hi*lo + lo*hi bf16 passes.
// 128x128 tile per CTA, 8 warps (warp tile 32x64), K-chunks of 32,
// cp.async double-buffered SMEM. Row stride 40 bf16 -> conflict-free ldmatrix.
#define TSTR      40
#define TILE_B    (128 * TSTR * 2)          // 10240 B per tile
#define BUF_B     (4 * TILE_B)              // 40960 B per buffer
#define TC_SMEM   (2 * BUF_B)               // 81920 B

__global__ __launch_bounds__(256) void tc_gemm(
    const __nv_bfloat16* __restrict__ Ahi, const __nv_bfloat16* __restrict__ Alo,
    const __nv_bfloat16* __restrict__ Bhi, const __nv_bfloat16* __restrict__ Blo,
    const float* __restrict__ bias, float* __restrict__ C, int K, int N)
{
    extern __shared__ __align__(16) char sm[];
    const uint32_t sb = smem_u32(sm);
    const int tid = threadIdx.x, warp = tid >> 5, lane = tid & 31;
    const int bn = blockIdx.x, bm = blockIdx.y;
    const int wm = warp & 3, wn = warp >> 2;     // 4x2 warps -> 128 x 128

    const char* srcs[4] = {
        (const char*)(Ahi + (size_t)(bm * 128) * K),
        (const char*)(Alo + (size_t)(bm * 128) * K),
        (const char*)(Bhi + (size_t)(bn * 128) * K),
        (const char*)(Blo + (size_t)(bn * 128) * K)};

    const int NC = K >> 5;                        // chunks of 32 k
    const int ldRow = tid >> 1;                   // 0..127
    const int ldSeg = (tid & 1) * 2;              // 0 or 2 (two 16B segs each)

    // fragment address components (per lane)
    const int lg = lane >> 3, lr = lane & 7;
    const int aRowOff = (lg & 1) * 8 + lr, aKOff = (lg >> 1) * 16;   // bytes
    const int bRowOff = (lg >> 1) * 8 + lr, bKOff = (lg & 1) * 16;

    float acc[2][8][4];
    #pragma unroll
    for (int i = 0; i < 2; i++)
        #pragma unroll
        for (int j = 0; j < 8; j++)
            #pragma unroll
            for (int q = 0; q < 4; q++) acc[i][j][q] = 0.f;

    // ---- preload chunk 0 into buffer 0 ----
    #pragma unroll
    for (int t = 0; t < 4; t++)
        #pragma unroll
        for (int s = 0; s < 2; s++)
            cp_async16(sb + t * TILE_B + ldRow * (TSTR * 2) + (ldSeg + s) * 16,
                       srcs[t] + (size_t)ldRow * K * 2 + (ldSeg + s) * 16);
    cp_commit();

    for (int ch = 0; ch < NC; ch++) {
        const uint32_t buf = sb + (ch & 1) * BUF_B;
        __syncthreads();                          // done reading target buffer
        if (ch + 1 < NC) {
            const uint32_t nb = sb + ((ch + 1) & 1) * BUF_B;
            const size_t go = (size_t)(ch + 1) * 64;   // 32 bf16 = 64 B
            #pragma unroll
            for (int t = 0; t < 4; t++)
                #pragma unroll
                for (int s = 0; s < 2; s++)
                    cp_async16(nb + t * TILE_B + ldRow * (TSTR * 2) + (ldSeg + s) * 16,
                               srcs[t] + (size_t)ldRow * K * 2 + go + (ldSeg + s) * 16);
        }
        cp_commit();
        cp_wait1();                               // chunk ch resident
        __syncthreads();

        #pragma unroll
        for (int ks = 0; ks < 2; ks++) {
            const int kb = ks * 32;               // byte offset of k16 subtile
            uint32_t ah[2][4], al[2][4], bh[4][4], bl[4][4];
            #pragma unroll
            for (int i = 0; i < 2; i++) {
                uint32_t ro = (wm * 32 + i * 16 + aRowOff) * (TSTR * 2) + kb + aKOff;
                ldmx4(ah[i], buf + 0 * TILE_B + ro);
                ldmx4(al[i], buf + 1 * TILE_B + ro);
            }
            #pragma unroll
            for (int j = 0; j < 4; j++) {
                uint32_t ro = (wn * 64 + j * 16 + bRowOff) * (TSTR * 2) + kb + bKOff;
                ldmx4(bh[j], buf + 2 * TILE_B + ro);
                ldmx4(bl[j], buf + 3 * TILE_B + ro);
            }
            #pragma unroll
            for (int i = 0; i < 2; i++)
                #pragma unroll
                for (int j = 0; j < 8; j++) {
                    const uint32_t* ph = &bh[j >> 1][(j & 1) * 2];
                    const uint32_t* pl = &bl[j >> 1][(j & 1) * 2];
                    mma16816(acc[i][j], ah[i], ph);
                    mma16816(acc[i][j], ah[i], pl);
                    mma16816(acc[i][j], al[i], ph);
                }
        }
    }

    // ---- epilogue: bias + direct float2 stores ----
    const int cr = lane >> 2, cc = (lane & 3) * 2;
    #pragma unroll
    for (int j = 0; j < 8; j++) {
        const int col = bn * 128 + wn * 64 + j * 8 + cc;
        const float b0 = __ldg(&bias[col]), b1 = __ldg(&bias[col + 1]);
        #pragma unroll
        for (int i = 0; i < 2; i++) {
            const int r0 = bm * 128 + wm * 32 + i * 16 + cr;
            float2 v0 = {acc[i][j][0] + b0, acc[i][j][1] + b1};
            float2 v1 = {acc[i][j][2] + b0, acc[i][j][3] + b1};
            *(float2*)&C[(size_t)r0 * N + col]       = v0;
            *(float2*)&C[(size_t)(r0 + 8) * N + col] = v1;
        }
    }
}

// --------------------- persistent LSTM scan (one per layer) ----------------
template <int H, int JR>
__global__ __launch_bounds__(256) void lstm_scan(
    const float* __restrict__ px,     // [T*32, 4H]
    const float* __restrict__ wh,     // [4H, H]
    const float* __restrict__ bh,     // [4H]
    const unsigned char* __restrict__ rm,
    float* __restrict__ hA, float* __restrict__ hB,
    float* __restrict__ c,
    float* __restrict__ y,            // [T*32, H]
    unsigned int* __restrict__ bar)
{
    constexpr int ROWS = 4 * JR;
    constexpr int TMr  = ROWS / 8;
    constexpr int KC   = H / 4;
    constexpr int NT   = KC / 32;
    constexpr int G    = 4 * H;
    constexpr int WSTR = ROWS + 1;
    constexpr int NW4  = ROWS * 8 / 64;
    static_assert(ROWS % 8 == 0 && KC % 32 == 0, "tiling");

    __shared__ __align__(16) float hs[4][32][36];
    constexpr int WS_FLOATS = 4 * 32 * WSTR;
    constexpr int PS_FLOATS = 4 * ROWS * 32;
    __shared__ __align__(16) float wsps[(WS_FLOATS > PS_FLOATS) ? WS_FLOATS
                                                                : PS_FLOATS];

    const int tid = threadIdx.x;
    const int kq  = tid >> 6;
    const int f   = tid & 63;
    const int rg  = (tid >> 3) & 7;
    const int bq  = tid & 7;
    const int r0  = rg * TMr;
    const int b0  = bq * 4;
    const int j0  = blockIdx.x * JR;
    const unsigned ncta = gridDim.x;

    for (int t = 0; t < T_LEN; t++) {
        const float* hin  = (t & 1) ? hB : hA;
        float*       hout = (t & 1) ? hA : hB;

        float4 wv[NW4], hv[4];
        {
            const int kbase = kq * KC;
            #pragma unroll
            for (int i = 0; i < NW4; i++) {
                int flat = f + i * 64, lr2 = flat >> 3, k4 = flat & 7;
                int grow = (lr2 / JR) * H + j0 + (lr2 % JR);
                wv[i] = *(const float4*)&wh[(size_t)grow * H + kbase + k4 * 4];
            }
            #pragma unroll
            for (int i = 0; i < 4; i++) {
                int flat = f + i * 64, b = flat >> 3, k4 = flat & 7;
                float4 v = __ldcg((const float4*)&hin[(size_t)b * H + kbase + k4 * 4]);
                if (rm[t * 32 + b]) { v.x = 0.f; v.y = 0.f; v.z = 0.f; v.w = 0.f; }
                hv[i] = v;
            }
        }

        float acc[TMr][4];
        #pragma unroll
        for (int i = 0; i < TMr; i++)
            #pragma unroll
            for (int j = 0; j < 4; j++) acc[i][j] = 0.f;

        for (int tile = 0; tile < NT; tile++) {
            __syncthreads();
            #pragma unroll
            for (int i = 0; i < NW4; i++) {
                int flat = f + i * 64, lr2 = flat >> 3, k4 = flat & 7;
                float* w = &wsps[kq * (32 * WSTR) + (k4 * 4) * WSTR + lr2];
                w[0 * WSTR] = wv[i].x; w[1 * WSTR] = wv[i].y;
                w[2 * WSTR] = wv[i].z; w[3 * WSTR] = wv[i].w;
            }
            #pragma unroll
            for (int i = 0; i < 4; i++) {
                int flat = f + i * 64, b = flat >> 3, k4 = flat & 7;
                hs[kq][k4 * 4 + 0][b] = hv[i].x;
                hs[kq][k4 * 4 + 1][b] = hv[i].y;
                hs[kq][k4 * 4 + 2][b] = hv[i].z;
                hs[kq][k4 * 4 + 3][b] = hv[i].w;
            }
            __syncthreads();

            if (tile + 1 < NT) {
                const int k0 = kq * KC + (tile + 1) * 32;
                #pragma unroll
                for (int i = 0; i < NW4; i++) {
                    int flat = f + i * 64, lr2 = flat >> 3, k4 = flat & 7;
                    int grow = (lr2 / JR) * H + j0 + (lr2 % JR);
                    wv[i] = *(const float4*)&wh[(size_t)grow * H + k0 + k4 * 4];
                }
                #pragma unroll
                for (int i = 0; i < 4; i++) {
                    int flat = f + i * 64, b = flat >> 3, k4 = flat & 7;
                    float4 v = __ldcg((const float4*)&hin[(size_t)b * H + k0 + k4 * 4]);
                    if (rm[t * 32 + b]) { v.x = 0.f; v.y = 0.f; v.z = 0.f; v.w = 0.f; }
                    hv[i] = v;
                }
            }

            #pragma unroll
            for (int kk = 0; kk < 32; kk++) {
                float4 hh = *(const float4*)&hs[kq][kk][b0];
                float wr[TMr];
                #pragma unroll
                for (int i = 0; i < TMr; i++)
                    wr[i] = wsps[kq * (32 * WSTR) + kk * WSTR + r0 + i];
                #pragma unroll
                for (int i = 0; i < TMr; i++) {
                    acc[i][0] = fmaf(wr[i], hh.x, acc[i][0]);
                    acc[i][1] = fmaf(wr[i], hh.y, acc[i][1]);
                    acc[i][2] = fmaf(wr[i], hh.z, acc[i][2]);
                    acc[i][3] = fmaf(wr[i], hh.w, acc[i][3]);
                }
            }
        }

        __syncthreads();
        #pragma unroll
        for (int i = 0; i < TMr; i++)
            #pragma unroll
            for (int j = 0; j < 4; j++)
                wsps[kq * (ROWS * 32) + (r0 + i) * 32 + b0 + j] = acc[i][j];
        __syncthreads();

        for (int e = tid; e < JR * 32; e += 256) {
            int jj = e >> 5, b = e & 31;
            int j = j0 + jj;
            float pre[4];
            #pragma unroll
            for (int g = 0; g < 4; g++) {
                int r = g * JR + jj;
                float s = bh[g * H + j]
                        + px[(size_t)(t * 32 + b) * G + g * H + j];
                #pragma unroll
                for (int q = 0; q < 4; q++)
                    s += wsps[q * (ROWS * 32) + r * 32 + b];
                pre[g] = s;
            }
            float ig = 1.f / (1.f + expf(-pre[0]));
            float fg = 1.f / (1.f + expf(-pre[1]));
            float og = 1.f / (1.f + expf(-pre[2]));
            float gg = tanhf(pre[3]);
            float cold = rm[t * 32 + b] ? 0.f : c[(size_t)b * H + j];
            float cn = fg * cold + ig * gg;
            float hn = og * tanhf(cn);
            c[(size_t)b * H + j]    = cn;
            hout[(size_t)b * H + j] = hn;
            y[(size_t)(t * 32 + b) * H + j] = hn;
        }

        if (t + 1 < T_LEN) {
            __threadfence();
            __syncthreads();
            if (tid == 0) {
                atomicAdd(bar, 1u);
                unsigned target = (unsigned)(t + 1) * ncta;
                while (*(volatile unsigned int*)bar < target) { }
            }
            __syncthreads();
        }
    }
}

// ------------------------------- launch -------------------------------------
extern "C" void kernel_launch(void* const* d_in, const int* in_sizes, int n_in,
                              void* d_out, int out_size)
{
    (void)in_sizes; (void)n_in; (void)out_size;
    const float* x   = (const float*)d_in[0];
    const int*   tok = (const int*)d_in[1];
    const float* wi[3] = {(const float*)d_in[2], (const float*)d_in[6],  (const float*)d_in[10]};
    const float* bi[3] = {(const float*)d_in[3], (const float*)d_in[7],  (const float*)d_in[11]};
    const float* wh[3] = {(const float*)d_in[4], (const float*)d_in[8],  (const float*)d_in[12]};
    const float* bh[3] = {(const float*)d_in[5], (const float*)d_in[9],  (const float*)d_in[13]};
    float* out = (float*)d_out;

    float *px = nullptr, *y0 = nullptr, *y1 = nullptr, *hA = nullptr,
          *hB = nullptr, *cb = nullptr;
    unsigned char* rmp = nullptr;
    unsigned int* bar = nullptr;
    __nv_bfloat16 *ahi = nullptr, *alo = nullptr, *bhi = nullptr, *blo = nullptr;
    cudaGetSymbolAddress((void**)&px,  g_px);
    cudaGetSymbolAddress((void**)&y0,  g_y0);
    cudaGetSymbolAddress((void**)&y1,  g_y1);
    cudaGetSymbolAddress((void**)&hA,  g_hA);
    cudaGetSymbolAddress((void**)&hB,  g_hB);
    cudaGetSymbolAddress((void**)&cb,  g_c);
    cudaGetSymbolAddress((void**)&rmp, g_rm);
    cudaGetSymbolAddress((void**)&bar, g_bar);
    cudaGetSymbolAddress((void**)&ahi, g_ahi);
    cudaGetSymbolAddress((void**)&alo, g_alo);
    cudaGetSymbolAddress((void**)&bhi, g_bhi);
    cudaGetSymbolAddress((void**)&blo, g_blo);

    cudaFuncSetAttribute(tc_gemm, cudaFuncAttributeMaxDynamicSharedMemorySize,
                         TC_SMEM);

    setup_rm<<<64, 256>>>(tok, rmp);

    const float* lin[3] = {x, y0, y1};
    float*       lys[3] = {y0, y1, out};
    const int Hs[3] = {HHID, HHID, DIN};
    const int Ks[3] = {DIN, HHID, HHID};

    for (int l = 0; l < 3; l++) {
        const int H = Hs[l], G = 4 * H, K = Ks[l];
        const int n = BATCH * H;
        init_layer<<<(n + 255) / 256, 256>>>(hA, hB, cb, bar, n);

        // bf16 hi/lo splits of A (layer input) and B (wi)
        const int na4 = (16384 * K) / 4;
        const int nb4 = (G * K) / 4;
        cvt_split<<<(na4 + 255) / 256, 256>>>(lin[l], ahi, alo, na4);
        cvt_split<<<(nb4 + 255) / 256, 256>>>(wi[l], bhi, blo, nb4);

        // px = A @ B^T + bias via mma.sync (3-pass bf16 split)
        tc_gemm<<<dim3(G / 128, 16384 / 128), 256, TC_SMEM>>>(
            ahi, alo, bhi, blo, bi[l], px, K, G);

        if (l < 2) {
            lstm_scan<HHID, 10><<<128, 256>>>(px, wh[l], bh[l], rmp,
                                              hA, hB, cb, lys[l], bar);
        } else {
            lstm_scan<DIN, 4><<<128, 256>>>(px, wh[l], bh[l], rmp,
                                            hA, hB, cb, lys[l], bar);
        }
    }

    // T_LEN even -> final h lives in hA; append h_last, c_last after y2
    cudaMemcpyAsync(out + 8388608,         hA, BATCH * DIN * sizeof(float),
                    cudaMemcpyDeviceToDevice);
    cudaMemcpyAsync(out + 8388608 + 16384, cb, BATCH * DIN * sizeof(float),
                    cudaMemcpyDeviceToDevice);
}

// round 6
// speedup vs baseline: 1.3126x; 1.2206x over previous
#include <cuda_runtime.h>
#include <cuda_bf16.h>
#include <cstdint>
#include <cstddef>

// ---------------------------------------------------------------------------
// ProteinAWDLSTM: 3-layer LSTM with token resets.
//   T=512, B=32, D_IN=512, H_HID=1280
// Per layer:
//   1) split inputs/weights into bf16 hi+lo
//   2) px = x @ wi^T + bi  via mma.sync bf16 GEMM (3-pass hi/lo, fp32 acc)
//   3) persistent scan kernel: SMEM-resident weights, SMEM-resident c,
//      px register prefetch, fast-math gates, 1 grid barrier/step.
// ---------------------------------------------------------------------------

#define T_LEN 512
#define BATCH 32
#define DIN   512
#define HHID  1280

// -------------------- device scratch (no allocs allowed) -------------------
__device__ float g_px [16384 * 5120];        // px for current layer
__device__ float g_y0 [16384 * 1280];        // layer0 out / layer1 in
__device__ float g_y1 [16384 * 1280];        // layer1 out / layer2 in
__device__ float g_hA [BATCH * HHID];
__device__ float g_hB [BATCH * HHID];
__device__ float g_c  [BATCH * HHID];
__device__ unsigned char g_rm[T_LEN * BATCH];
__device__ unsigned int  g_bar;
__device__ __nv_bfloat16 g_ahi[16384 * 1280];
__device__ __nv_bfloat16 g_alo[16384 * 1280];
__device__ __nv_bfloat16 g_bhi[5120 * 1280];
__device__ __nv_bfloat16 g_blo[5120 * 1280];

// --------------------------- PTX helpers (baseline) -------------------------
__device__ __forceinline__ uint32_t smem_u32(const void* p) {
    uint32_t a;
    asm("{ .reg .u64 t; cvta.to.shared.u64 t, %1; cvt.u32.u64 %0, t; }"
        : "=r"(a) : "l"(p));
    return a;
}
__device__ __forceinline__ void cp_async16(uint32_t dst, const void* src) {
    asm volatile("cp.async.cg.shared.global [%0], [%1], 16;"
                 :: "r"(dst), "l"(src) : "memory");
}
__device__ __forceinline__ void cp_commit() {
    asm volatile("cp.async.commit_group;" ::: "memory");
}
__device__ __forceinline__ void cp_wait1() {
    asm volatile("cp.async.wait_group 1;" ::: "memory");
}
__device__ __forceinline__ void ldmx4(uint32_t* r, uint32_t addr) {
    asm volatile("ldmatrix.sync.aligned.m8n8.x4.shared.b16 {%0,%1,%2,%3}, [%4];"
                 : "=r"(r[0]), "=r"(r[1]), "=r"(r[2]), "=r"(r[3]) : "r"(addr));
}
__device__ __forceinline__ void mma16816(float* c, const uint32_t* a,
                                         const uint32_t* b) {
    asm volatile("mma.sync.aligned.m16n8k16.row.col.f32.bf16.bf16.f32 "
                 "{%0,%1,%2,%3}, {%4,%5,%6,%7}, {%8,%9}, {%0,%1,%2,%3};"
                 : "+f"(c[0]), "+f"(c[1]), "+f"(c[2]), "+f"(c[3])
                 : "r"(a[0]), "r"(a[1]), "r"(a[2]), "r"(a[3]),
                   "r"(b[0]), "r"(b[1]));
}

// ------------------------------- setup -------------------------------------
__global__ __launch_bounds__(256) void setup_rm(const int* __restrict__ tok,
                                                unsigned char* __restrict__ rm) {
    int idx = blockIdx.x * 256 + threadIdx.x;      // < 16384
    int t = idx >> 5, b = idx & 31;
    rm[idx] = (t >= 2 && tok[(t - 1) * 32 + b] == 0) ? 1 : 0;
}

__global__ __launch_bounds__(256) void init_layer(float* __restrict__ hA,
                                                  float* __restrict__ hB,
                                                  unsigned int* __restrict__ bar,
                                                  int n) {
    int i = blockIdx.x * 256 + threadIdx.x;
    if (i < n) { hA[i] = 0.f; hB[i] = 0.f; }
    if (i == 0) *bar = 0u;
}

// ------------------------- fp32 -> bf16 hi/lo split --------------------------
__global__ __launch_bounds__(256) void cvt_split(const float* __restrict__ x,
                                                 __nv_bfloat16* __restrict__ hi,
                                                 __nv_bfloat16* __restrict__ lo,
                                                 int n4) {
    int i = blockIdx.x * 256 + threadIdx.x;
    if (i >= n4) return;
    float4 v = ((const float4*)x)[i];
    __nv_bfloat16 h0 = __float2bfloat16(v.x);
    __nv_bfloat16 h1 = __float2bfloat16(v.y);
    __nv_bfloat16 h2 = __float2bfloat16(v.z);
    __nv_bfloat16 h3 = __float2bfloat16(v.w);
    __nv_bfloat16 l0 = __float2bfloat16(v.x - __bfloat162float(h0));
    __nv_bfloat16 l1 = __float2bfloat16(v.y - __bfloat162float(h1));
    __nv_bfloat16 l2 = __float2bfloat16(v.z - __bfloat162float(h2));
    __nv_bfloat16 l3 = __float2bfloat16(v.w - __bfloat162float(h3));
    ((__nv_bfloat162*)hi)[2 * i]     = __nv_bfloat162(h0, h1);
    ((__nv_bfloat162*)hi)[2 * i + 1] = __nv_bfloat162(h2, h3);
    ((__nv_bfloat162*)lo)[2 * i]     = __nv_bfloat162(l0, l1);
    ((__nv_bfloat162*)lo)[2 * i + 1] = __nv_bfloat162(l2, l3);
}

// ----------------------- mma.sync bf16 split GEMM ----------------------------
// C[M,N] = A[M,K] @ B[N,K]^T + bias, via hi*hi + hi*lo + lo*hi bf16 passes.
#define TSTR      40
#define TILE_B    (128 * TSTR * 2)          // 10240 B per tile
#define BUF_B     (4 * TILE_B)              // 40960 B per buffer
#define TC_SMEM   (2 * BUF_B)               // 81920 B

__global__ __launch_bounds__(256) void tc_gemm(
    const __nv_bfloat16* __restrict__ Ahi, const __nv_bfloat16* __restrict__ Alo,
    const __nv_bfloat16* __restrict__ Bhi, const __nv_bfloat16* __restrict__ Blo,
    const float* __restrict__ bias, float* __restrict__ C, int K, int N)
{
    extern __shared__ __align__(16) char sm[];
    const uint32_t sb = smem_u32(sm);
    const int tid = threadIdx.x, warp = tid >> 5, lane = tid & 31;
    const int bn = blockIdx.x, bm = blockIdx.y;
    const int wm = warp & 3, wn = warp >> 2;     // 4x2 warps -> 128 x 128

    const char* srcs[4] = {
        (const char*)(Ahi + (size_t)(bm * 128) * K),
        (const char*)(Alo + (size_t)(bm * 128) * K),
        (const char*)(Bhi + (size_t)(bn * 128) * K),
        (const char*)(Blo + (size_t)(bn * 128) * K)};

    const int NC = K >> 5;                        // chunks of 32 k
    const int ldRow = tid >> 1;                   // 0..127
    const int ldSeg = (tid & 1) * 2;              // 0 or 2

    const int lg = lane >> 3, lr = lane & 7;
    const int aRowOff = (lg & 1) * 8 + lr, aKOff = (lg >> 1) * 16;
    const int bRowOff = (lg >> 1) * 8 + lr, bKOff = (lg & 1) * 16;

    float acc[2][8][4];
    #pragma unroll
    for (int i = 0; i < 2; i++)
        #pragma unroll
        for (int j = 0; j < 8; j++)
            #pragma unroll
            for (int q = 0; q < 4; q++) acc[i][j][q] = 0.f;

    #pragma unroll
    for (int t = 0; t < 4; t++)
        #pragma unroll
        for (int s = 0; s < 2; s++)
            cp_async16(sb + t * TILE_B + ldRow * (TSTR * 2) + (ldSeg + s) * 16,
                       srcs[t] + (size_t)ldRow * K * 2 + (ldSeg + s) * 16);
    cp_commit();

    for (int ch = 0; ch < NC; ch++) {
        const uint32_t buf = sb + (ch & 1) * BUF_B;
        __syncthreads();
        if (ch + 1 < NC) {
            const uint32_t nb = sb + ((ch + 1) & 1) * BUF_B;
            const size_t go = (size_t)(ch + 1) * 64;
            #pragma unroll
            for (int t = 0; t < 4; t++)
                #pragma unroll
                for (int s = 0; s < 2; s++)
                    cp_async16(nb + t * TILE_B + ldRow * (TSTR * 2) + (ldSeg + s) * 16,
                               srcs[t] + (size_t)ldRow * K * 2 + go + (ldSeg + s) * 16);
        }
        cp_commit();
        cp_wait1();
        __syncthreads();

        #pragma unroll
        for (int ks = 0; ks < 2; ks++) {
            const int kb = ks * 32;
            uint32_t ah[2][4], al[2][4], bh[4][4], bl[4][4];
            #pragma unroll
            for (int i = 0; i < 2; i++) {
                uint32_t ro = (wm * 32 + i * 16 + aRowOff) * (TSTR * 2) + kb + aKOff;
                ldmx4(ah[i], buf + 0 * TILE_B + ro);
                ldmx4(al[i], buf + 1 * TILE_B + ro);
            }
            #pragma unroll
            for (int j = 0; j < 4; j++) {
                uint32_t ro = (wn * 64 + j * 16 + bRowOff) * (TSTR * 2) + kb + bKOff;
                ldmx4(bh[j], buf + 2 * TILE_B + ro);
                ldmx4(bl[j], buf + 3 * TILE_B + ro);
            }
            #pragma unroll
            for (int i = 0; i < 2; i++)
                #pragma unroll
                for (int j = 0; j < 8; j++) {
                    const uint32_t* ph = &bh[j >> 1][(j & 1) * 2];
                    const uint32_t* pl = &bl[j >> 1][(j & 1) * 2];
                    mma16816(acc[i][j], ah[i], ph);
                    mma16816(acc[i][j], ah[i], pl);
                    mma16816(acc[i][j], al[i], ph);
                }
        }
    }

    const int cr = lane >> 2, cc = (lane & 3) * 2;
    #pragma unroll
    for (int j = 0; j < 8; j++) {
        const int col = bn * 128 + wn * 64 + j * 8 + cc;
        const float b0 = __ldg(&bias[col]), b1 = __ldg(&bias[col + 1]);
        #pragma unroll
        for (int i = 0; i < 2; i++) {
            const int r0 = bm * 128 + wm * 32 + i * 16 + cr;
            float2 v0 = {acc[i][j][0] + b0, acc[i][j][1] + b1};
            float2 v1 = {acc[i][j][2] + b0, acc[i][j][3] + b1};
            *(float2*)&C[(size_t)r0 * N + col]       = v0;
            *(float2*)&C[(size_t)(r0 + 8) * N + col] = v1;
        }
    }
}

// --------------------- persistent LSTM scan (one per layer) ----------------
// 128 CTAs x 256 thr. CTA owns JR hidden cols (all gates, all batches, full K).
// Weights SMEM-resident ([ROWS][H], read as float4), c SMEM-resident,
// px prefetched to registers, fast-math gates, 1 grid barrier/step.
template <int H, int JR>
__global__ __launch_bounds__(256) void lstm_scan(
    const float* __restrict__ px,     // [T*32, 4H]
    const float* __restrict__ wh,     // [4H, H]
    const float* __restrict__ bh,     // [4H]
    const unsigned char* __restrict__ rm,
    float* __restrict__ hA, float* __restrict__ hB,
    float* __restrict__ c,
    float* __restrict__ y,            // [T*32, H]
    unsigned int* __restrict__ bar)
{
    constexpr int ROWS = 4 * JR;          // 40 or 16
    constexpr int TMr  = ROWS / 8;        // 5 or 2
    constexpr int KC   = H / 4;
    constexpr int NT   = KC / 32;
    constexpr int G    = 4 * H;
    constexpr int HS_STR = 36, PS_STR = 33;
    constexpr int HS_BLK = 32 * HS_STR;
    constexpr int PS_BLK = ROWS * PS_STR;
    constexpr int UNION_FL = (4 * HS_BLK > 4 * PS_BLK) ? 4 * HS_BLK : 4 * PS_BLK;
    constexpr int NE = (JR * 32 + 255) / 256;
    static_assert(ROWS % 8 == 0 && KC % 32 == 0, "tiling");

    extern __shared__ __align__(16) float smf[];
    float* wres = smf;                    // [ROWS][H]
    float* un   = smf + ROWS * H;         // hs (during tiles) / ps (after)
    float* c_s  = un + UNION_FL;          // [JR*32]

    const int tid = threadIdx.x;
    const int kq  = tid >> 6;             // K quarter
    const int f   = tid & 63;
    const int rg  = (tid >> 3) & 7;
    const int bq  = tid & 7;
    const int r0  = rg * TMr;
    const int b0  = bq * 4;
    const int j0  = blockIdx.x * JR;
    const unsigned ncta = gridDim.x;

    // ---- preload weights (coalesced gmem reads) + init c ----
    for (int idx = tid; idx < ROWS * H; idx += 256) {
        int lr = idx / H, k = idx - lr * H;
        int grow = (lr / JR) * H + j0 + (lr % JR);
        wres[lr * H + k] = wh[(size_t)grow * H + k];
    }
    for (int i = tid; i < JR * 32; i += 256) c_s[i] = 0.f;

    // ---- per-thread epilogue constants ----
    int ej[NE], eb[NE]; bool ev[NE]; float ebh[NE][4];
    #pragma unroll
    for (int n = 0; n < NE; n++) {
        int e = tid + n * 256;
        ev[n] = (e < JR * 32);
        ej[n] = e >> 5;
        eb[n] = e & 31;
        if (ev[n]) {
            #pragma unroll
            for (int g = 0; g < 4; g++)
                ebh[n][g] = bh[g * H + j0 + ej[n]];
        }
    }
    __syncthreads();

    for (int t = 0; t < T_LEN; t++) {
        const float* hin  = (t & 1) ? hB : hA;
        float*       hout = (t & 1) ? hA : hB;

        unsigned char rmS[4];
        #pragma unroll
        for (int i = 0; i < 4; i++) rmS[i] = rm[t * 32 + (f >> 3) + i * 8];

        // prefetch h tile 0
        float4 hv[4];
        #pragma unroll
        for (int i = 0; i < 4; i++) {
            int b = (f >> 3) + i * 8, k4 = f & 7;
            float4 v = __ldcg((const float4*)&hin[(size_t)b * H + kq * KC + k4 * 4]);
            if (rmS[i]) { v.x = 0.f; v.y = 0.f; v.z = 0.f; v.w = 0.f; }
            hv[i] = v;
        }

        // prefetch px (DRAM latency hidden behind the matvec)
        float pxv[NE][4]; unsigned char erm[NE];
        #pragma unroll
        for (int n = 0; n < NE; n++) {
            if (ev[n]) {
                erm[n] = rm[t * 32 + eb[n]];
                #pragma unroll
                for (int g = 0; g < 4; g++)
                    pxv[n][g] = __ldcg(&px[(size_t)(t * 32 + eb[n]) * G + g * H + j0 + ej[n]]);
            }
        }

        float acc[TMr][4];
        #pragma unroll
        for (int i = 0; i < TMr; i++)
            #pragma unroll
            for (int j = 0; j < 4; j++) acc[i][j] = 0.f;

        for (int tile = 0; tile < NT; tile++) {
            __syncthreads();              // prev tile compute done
            #pragma unroll
            for (int i = 0; i < 4; i++) {
                int b = (f >> 3) + i * 8, k4 = f & 7;
                float* hp = &un[kq * HS_BLK + (k4 * 4) * HS_STR + b];
                hp[0 * HS_STR] = hv[i].x; hp[1 * HS_STR] = hv[i].y;
                hp[2 * HS_STR] = hv[i].z; hp[3 * HS_STR] = hv[i].w;
            }
            __syncthreads();

            if (tile + 1 < NT) {          // prefetch next h tile
                const int k0 = kq * KC + (tile + 1) * 32;
                #pragma unroll
                for (int i = 0; i < 4; i++) {
                    int b = (f >> 3) + i * 8, k4 = f & 7;
                    float4 v = __ldcg((const float4*)&hin[(size_t)b * H + k0 + k4 * 4]);
                    if (rmS[i]) { v.x = 0.f; v.y = 0.f; v.z = 0.f; v.w = 0.f; }
                    hv[i] = v;
                }
            }

            const int kbase = kq * KC + tile * 32;
            #pragma unroll
            for (int k4 = 0; k4 < 8; k4++) {
                float4 wv[TMr];
                #pragma unroll
                for (int i = 0; i < TMr; i++)
                    wv[i] = *(const float4*)&wres[(r0 + i) * H + kbase + k4 * 4];
                float4 hh[4];
                #pragma unroll
                for (int j = 0; j < 4; j++)
                    hh[j] = *(const float4*)&un[kq * HS_BLK + (k4 * 4 + j) * HS_STR + b0];
                #pragma unroll
                for (int i = 0; i < TMr; i++) {
                    acc[i][0] = fmaf(wv[i].x, hh[0].x, acc[i][0]);
                    acc[i][0] = fmaf(wv[i].y, hh[1].x, acc[i][0]);
                    acc[i][0] = fmaf(wv[i].z, hh[2].x, acc[i][0]);
                    acc[i][0] = fmaf(wv[i].w, hh[3].x, acc[i][0]);
                    acc[i][1] = fmaf(wv[i].x, hh[0].y, acc[i][1]);
                    acc[i][1] = fmaf(wv[i].y, hh[1].y, acc[i][1]);
                    acc[i][1] = fmaf(wv[i].z, hh[2].y, acc[i][1]);
                    acc[i][1] = fmaf(wv[i].w, hh[3].y, acc[i][1]);
                    acc[i][2] = fmaf(wv[i].x, hh[0].z, acc[i][2]);
                    acc[i][2] = fmaf(wv[i].y, hh[1].z, acc[i][2]);
                    acc[i][2] = fmaf(wv[i].z, hh[2].z, acc[i][2]);
                    acc[i][2] = fmaf(wv[i].w, hh[3].z, acc[i][2]);
                    acc[i][3] = fmaf(wv[i].x, hh[0].w, acc[i][3]);
                    acc[i][3] = fmaf(wv[i].y, hh[1].w, acc[i][3]);
                    acc[i][3] = fmaf(wv[i].z, hh[2].w, acc[i][3]);
                    acc[i][3] = fmaf(wv[i].w, hh[3].w, acc[i][3]);
                }
            }
        }

        __syncthreads();                  // hs dead -> reuse region as ps
        #pragma unroll
        for (int i = 0; i < TMr; i++)
            #pragma unroll
            for (int j = 0; j < 4; j++)
                un[kq * PS_BLK + (r0 + i) * PS_STR + b0 + j] = acc[i][j];
        __syncthreads();

        // ---- epilogue ----
        #pragma unroll
        for (int n = 0; n < NE; n++) {
            if (!ev[n]) continue;
            float pre[4];
            #pragma unroll
            for (int g = 0; g < 4; g++) {
                float s = ebh[n][g] + pxv[n][g];
                int r = g * JR + ej[n];
                #pragma unroll
                for (int q = 0; q < 4; q++)
                    s += un[q * PS_BLK + r * PS_STR + eb[n]];
                pre[g] = s;
            }
            float ig = 1.f / (1.f + __expf(-pre[0]));
            float fg = 1.f / (1.f + __expf(-pre[1]));
            float og = 1.f / (1.f + __expf(-pre[2]));
            float gg = 2.f / (1.f + __expf(-2.f * pre[3])) - 1.f;
            float cold = erm[n] ? 0.f : c_s[ej[n] * 32 + eb[n]];
            float cn = fg * cold + ig * gg;
            float th = 2.f / (1.f + __expf(-2.f * cn)) - 1.f;
            float hn = og * th;
            c_s[ej[n] * 32 + eb[n]] = cn;
            hout[(size_t)eb[n] * H + j0 + ej[n]] = hn;
            y[(size_t)(t * 32 + eb[n]) * H + j0 + ej[n]] = hn;
        }

        // ---- grid barrier ----
        if (t + 1 < T_LEN) {
            __threadfence();
            __syncthreads();
            if (tid == 0) {
                atomicAdd(bar, 1u);
                unsigned target = (unsigned)(t + 1) * ncta;
                while (*(volatile unsigned int*)bar < target) { }
            }
            __syncthreads();
        }
    }

    // flush c (needed only for last layer's c_last output)
    #pragma unroll
    for (int n = 0; n < NE; n++)
        if (ev[n])
            c[(size_t)eb[n] * H + j0 + ej[n]] = c_s[ej[n] * 32 + eb[n]];
}

// ------------------------------- launch -------------------------------------
extern "C" void kernel_launch(void* const* d_in, const int* in_sizes, int n_in,
                              void* d_out, int out_size)
{
    (void)in_sizes; (void)n_in; (void)out_size;
    const float* x   = (const float*)d_in[0];
    const int*   tok = (const int*)d_in[1];
    const float* wi[3] = {(const float*)d_in[2], (const float*)d_in[6],  (const float*)d_in[10]};
    const float* bi[3] = {(const float*)d_in[3], (const float*)d_in[7],  (const float*)d_in[11]};
    const float* wh[3] = {(const float*)d_in[4], (const float*)d_in[8],  (const float*)d_in[12]};
    const float* bh[3] = {(const float*)d_in[5], (const float*)d_in[9],  (const float*)d_in[13]};
    float* out = (float*)d_out;

    float *px = nullptr, *y0 = nullptr, *y1 = nullptr, *hA = nullptr,
          *hB = nullptr, *cb = nullptr;
    unsigned char* rmp = nullptr;
    unsigned int* bar = nullptr;
    __nv_bfloat16 *ahi = nullptr, *alo = nullptr, *bhi = nullptr, *blo = nullptr;
    cudaGetSymbolAddress((void**)&px,  g_px);
    cudaGetSymbolAddress((void**)&y0,  g_y0);
    cudaGetSymbolAddress((void**)&y1,  g_y1);
    cudaGetSymbolAddress((void**)&hA,  g_hA);
    cudaGetSymbolAddress((void**)&hB,  g_hB);
    cudaGetSymbolAddress((void**)&cb,  g_c);
    cudaGetSymbolAddress((void**)&rmp, g_rm);
    cudaGetSymbolAddress((void**)&bar, g_bar);
    cudaGetSymbolAddress((void**)&ahi, g_ahi);
    cudaGetSymbolAddress((void**)&alo, g_alo);
    cudaGetSymbolAddress((void**)&bhi, g_bhi);
    cudaGetSymbolAddress((void**)&blo, g_blo);

    cudaFuncSetAttribute(tc_gemm, cudaFuncAttributeMaxDynamicSharedMemorySize,
                         TC_SMEM);
    // scan smem: l0/l1: (40*1280 + 5280 + 320)*4 = 227200 B
    //            l2:    (16*512  + 4608 + 128)*4 = 51712 B
    const int SCAN_SMEM_BIG   = (40 * 1280 + 5280 + 320) * 4;
    const int SCAN_SMEM_SMALL = (16 * 512 + 4608 + 128) * 4;
    cudaFuncSetAttribute(lstm_scan<HHID, 10>,
                         cudaFuncAttributeMaxDynamicSharedMemorySize, SCAN_SMEM_BIG);
    cudaFuncSetAttribute(lstm_scan<DIN, 4>,
                         cudaFuncAttributeMaxDynamicSharedMemorySize, SCAN_SMEM_SMALL);

    setup_rm<<<64, 256>>>(tok, rmp);

    const float* lin[3] = {x, y0, y1};
    float*       lys[3] = {y0, y1, out};
    const int Hs[3] = {HHID, HHID, DIN};
    const int Ks[3] = {DIN, HHID, HHID};

    for (int l = 0; l < 3; l++) {
        const int H = Hs[l], G = 4 * H, K = Ks[l];
        const int n = BATCH * H;
        init_layer<<<(n + 255) / 256, 256>>>(hA, hB, bar, n);

        const int na4 = (16384 * K) / 4;
        const int nb4 = (G * K) / 4;
        cvt_split<<<(na4 + 255) / 256, 256>>>(lin[l], ahi, alo, na4);
        cvt_split<<<(nb4 + 255) / 256, 256>>>(wi[l], bhi, blo, nb4);

        tc_gemm<<<dim3(G / 128, 16384 / 128), 256, TC_SMEM>>>(
            ahi, alo, bhi, blo, bi[l], px, K, G);

        if (l < 2) {
            lstm_scan<HHID, 10><<<128, 256, SCAN_SMEM_BIG>>>(
                px, wh[l], bh[l], rmp, hA, hB, cb, lys[l], bar);
        } else {
            lstm_scan<DIN, 4><<<128, 256, SCAN_SMEM_SMALL>>>(
                px, wh[l], bh[l], rmp, hA, hB, cb, lys[l], bar);
        }
    }

    // T_LEN even -> final h lives in hA; append h_last, c_last after y2
    cudaMemcpyAsync(out + 8388608,         hA, BATCH * DIN * sizeof(float),
                    cudaMemcpyDeviceToDevice);
    cudaMemcpyAsync(out + 8388608 + 16384, cb, BATCH * DIN * sizeof(float),
                    cudaMemcpyDeviceToDevice);
}

// round 9
// speedup vs baseline: 1.5094x; 1.1500x over previous
#include <cuda_runtime.h>
#include <cuda_bf16.h>
#include <cstdint>
#include <cstddef>

// ---------------------------------------------------------------------------
// ProteinAWDLSTM: 3-layer LSTM with token resets.
//   T=512, B=32, D_IN=512, H_HID=1280
// Per layer:
//   1) split inputs/weights into bf16 hi+lo
//   2) px = x @ wi^T + bi  via mma.sync bf16 GEMM (3-pass hi/lo, fp32 acc)
//   3) persistent scan: SMEM weights, SMEM c, px reg prefetch, fast gates,
//      packed fma.rn.f32x2 inner product (k-pairs in lanes), 1 barrier/step.
// (Round 8 = round 7 resubmitted verbatim: round-7 bench was an infra
//  failure, not a kernel signal.)
// ---------------------------------------------------------------------------

#define T_LEN 512
#define BATCH 32
#define DIN   512
#define HHID  1280

// -------------------- device scratch (no allocs allowed) -------------------
__device__ float g_px [16384 * 5120];        // px for current layer
__device__ float g_y0 [16384 * 1280];        // layer0 out / layer1 in
__device__ float g_y1 [16384 * 1280];        // layer1 out / layer2 in
__device__ float g_hA [BATCH * HHID];
__device__ float g_hB [BATCH * HHID];
__device__ float g_c  [BATCH * HHID];
__device__ unsigned char g_rm[T_LEN * BATCH];
__device__ unsigned int  g_bar;
__device__ __nv_bfloat16 g_ahi[16384 * 1280];
__device__ __nv_bfloat16 g_alo[16384 * 1280];
__device__ __nv_bfloat16 g_bhi[5120 * 1280];
__device__ __nv_bfloat16 g_blo[5120 * 1280];

// --------------------------- PTX helpers (baseline) -------------------------
__device__ __forceinline__ uint32_t smem_u32(const void* p) {
    uint32_t a;
    asm("{ .reg .u64 t; cvta.to.shared.u64 t, %1; cvt.u32.u64 %0, t; }"
        : "=r"(a) : "l"(p));
    return a;
}
__device__ __forceinline__ void cp_async16(uint32_t dst, const void* src) {
    asm volatile("cp.async.cg.shared.global [%0], [%1], 16;"
                 :: "r"(dst), "l"(src) : "memory");
}
__device__ __forceinline__ void cp_commit() {
    asm volatile("cp.async.commit_group;" ::: "memory");
}
__device__ __forceinline__ void cp_wait1() {
    asm volatile("cp.async.wait_group 1;" ::: "memory");
}
__device__ __forceinline__ void ldmx4(uint32_t* r, uint32_t addr) {
    asm volatile("ldmatrix.sync.aligned.m8n8.x4.shared.b16 {%0,%1,%2,%3}, [%4];"
                 : "=r"(r[0]), "=r"(r[1]), "=r"(r[2]), "=r"(r[3]) : "r"(addr));
}
__device__ __forceinline__ void mma16816(float* c, const uint32_t* a,
                                         const uint32_t* b) {
    asm volatile("mma.sync.aligned.m16n8k16.row.col.f32.bf16.bf16.f32 "
                 "{%0,%1,%2,%3}, {%4,%5,%6,%7}, {%8,%9}, {%0,%1,%2,%3};"
                 : "+f"(c[0]), "+f"(c[1]), "+f"(c[2]), "+f"(c[3])
                 : "r"(a[0]), "r"(a[1]), "r"(a[2]), "r"(a[3]),
                   "r"(b[0]), "r"(b[1]));
}
// packed fp32 pair FMA: d.lo += a.lo*b.lo, d.hi += a.hi*b.hi (sm_100+ base PTX)
__device__ __forceinline__ void ffma2(unsigned long long& acc,
                                      unsigned long long a,
                                      unsigned long long b) {
    asm("fma.rn.f32x2 %0, %1, %2, %0;" : "+l"(acc) : "l"(a), "l"(b));
}
__device__ __forceinline__ float unpack_sum(unsigned long long a) {
    return __uint_as_float((unsigned)a) + __uint_as_float((unsigned)(a >> 32));
}

// ------------------------------- setup -------------------------------------
__global__ __launch_bounds__(256) void setup_rm(const int* __restrict__ tok,
                                                unsigned char* __restrict__ rm) {
    int idx = blockIdx.x * 256 + threadIdx.x;      // < 16384
    int t = idx >> 5, b = idx & 31;
    rm[idx] = (t >= 2 && tok[(t - 1) * 32 + b] == 0) ? 1 : 0;
}

__global__ __launch_bounds__(256) void init_layer(float* __restrict__ hA,
                                                  float* __restrict__ hB,
                                                  unsigned int* __restrict__ bar,
                                                  int n) {
    int i = blockIdx.x * 256 + threadIdx.x;
    if (i < n) { hA[i] = 0.f; hB[i] = 0.f; }
    if (i == 0) *bar = 0u;
}

// ------------------------- fp32 -> bf16 hi/lo split --------------------------
__global__ __launch_bounds__(256) void cvt_split(const float* __restrict__ x,
                                                 __nv_bfloat16* __restrict__ hi,
                                                 __nv_bfloat16* __restrict__ lo,
                                                 int n4) {
    int i = blockIdx.x * 256 + threadIdx.x;
    if (i >= n4) return;
    float4 v = ((const float4*)x)[i];
    __nv_bfloat16 h0 = __float2bfloat16(v.x);
    __nv_bfloat16 h1 = __float2bfloat16(v.y);
    __nv_bfloat16 h2 = __float2bfloat16(v.z);
    __nv_bfloat16 h3 = __float2bfloat16(v.w);
    __nv_bfloat16 l0 = __float2bfloat16(v.x - __bfloat162float(h0));
    __nv_bfloat16 l1 = __float2bfloat16(v.y - __bfloat162float(h1));
    __nv_bfloat16 l2 = __float2bfloat16(v.z - __bfloat162float(h2));
    __nv_bfloat16 l3 = __float2bfloat16(v.w - __bfloat162float(h3));
    ((__nv_bfloat162*)hi)[2 * i]     = __nv_bfloat162(h0, h1);
    ((__nv_bfloat162*)hi)[2 * i + 1] = __nv_bfloat162(h2, h3);
    ((__nv_bfloat162*)lo)[2 * i]     = __nv_bfloat162(l0, l1);
    ((__nv_bfloat162*)lo)[2 * i + 1] = __nv_bfloat162(l2, l3);
}

// ----------------------- mma.sync bf16 split GEMM ----------------------------
#define TSTR      40
#define TILE_B    (128 * TSTR * 2)          // 10240 B per tile
#define BUF_B     (4 * TILE_B)              // 40960 B per buffer
#define TC_SMEM   (2 * BUF_B)               // 81920 B

__global__ __launch_bounds__(256) void tc_gemm(
    const __nv_bfloat16* __restrict__ Ahi, const __nv_bfloat16* __restrict__ Alo,
    const __nv_bfloat16* __restrict__ Bhi, const __nv_bfloat16* __restrict__ Blo,
    const float* __restrict__ bias, float* __restrict__ C, int K, int N)
{
    extern __shared__ __align__(16) char sm[];
    const uint32_t sb = smem_u32(sm);
    const int tid = threadIdx.x, warp = tid >> 5, lane = tid & 31;
    const int bn = blockIdx.x, bm = blockIdx.y;
    const int wm = warp & 3, wn = warp >> 2;     // 4x2 warps -> 128 x 128

    const char* srcs[4] = {
        (const char*)(Ahi + (size_t)(bm * 128) * K),
        (const char*)(Alo + (size_t)(bm * 128) * K),
        (const char*)(Bhi + (size_t)(bn * 128) * K),
        (const char*)(Blo + (size_t)(bn * 128) * K)};

    const int NC = K >> 5;                        // chunks of 32 k
    const int ldRow = tid >> 1;                   // 0..127
    const int ldSeg = (tid & 1) * 2;              // 0 or 2

    const int lg = lane >> 3, lr = lane & 7;
    const int aRowOff = (lg & 1) * 8 + lr, aKOff = (lg >> 1) * 16;
    const int bRowOff = (lg >> 1) * 8 + lr, bKOff = (lg & 1) * 16;

    float acc[2][8][4];
    #pragma unroll
    for (int i = 0; i < 2; i++)
        #pragma unroll
        for (int j = 0; j < 8; j++)
            #pragma unroll
            for (int q = 0; q < 4; q++) acc[i][j][q] = 0.f;

    #pragma unroll
    for (int t = 0; t < 4; t++)
        #pragma unroll
        for (int s = 0; s < 2; s++)
            cp_async16(sb + t * TILE_B + ldRow * (TSTR * 2) + (ldSeg + s) * 16,
                       srcs[t] + (size_t)ldRow * K * 2 + (ldSeg + s) * 16);
    cp_commit();

    for (int ch = 0; ch < NC; ch++) {
        const uint32_t buf = sb + (ch & 1) * BUF_B;
        __syncthreads();
        if (ch + 1 < NC) {
            const uint32_t nb = sb + ((ch + 1) & 1) * BUF_B;
            const size_t go = (size_t)(ch + 1) * 64;
            #pragma unroll
            for (int t = 0; t < 4; t++)
                #pragma unroll
                for (int s = 0; s < 2; s++)
                    cp_async16(nb + t * TILE_B + ldRow * (TSTR * 2) + (ldSeg + s) * 16,
                               srcs[t] + (size_t)ldRow * K * 2 + go + (ldSeg + s) * 16);
        }
        cp_commit();
        cp_wait1();
        __syncthreads();

        #pragma unroll
        for (int ks = 0; ks < 2; ks++) {
            const int kb = ks * 32;
            uint32_t ah[2][4], al[2][4], bh[4][4], bl[4][4];
            #pragma unroll
            for (int i = 0; i < 2; i++) {
                uint32_t ro = (wm * 32 + i * 16 + aRowOff) * (TSTR * 2) + kb + aKOff;
                ldmx4(ah[i], buf + 0 * TILE_B + ro);
                ldmx4(al[i], buf + 1 * TILE_B + ro);
            }
            #pragma unroll
            for (int j = 0; j < 4; j++) {
                uint32_t ro = (wn * 64 + j * 16 + bRowOff) * (TSTR * 2) + kb + bKOff;
                ldmx4(bh[j], buf + 2 * TILE_B + ro);
                ldmx4(bl[j], buf + 3 * TILE_B + ro);
            }
            #pragma unroll
            for (int i = 0; i < 2; i++)
                #pragma unroll
                for (int j = 0; j < 8; j++) {
                    const uint32_t* ph = &bh[j >> 1][(j & 1) * 2];
                    const uint32_t* pl = &bl[j >> 1][(j & 1) * 2];
                    mma16816(acc[i][j], ah[i], ph);
                    mma16816(acc[i][j], ah[i], pl);
                    mma16816(acc[i][j], al[i], ph);
                }
        }
    }

    const int cr = lane >> 2, cc = (lane & 3) * 2;
    #pragma unroll
    for (int j = 0; j < 8; j++) {
        const int col = bn * 128 + wn * 64 + j * 8 + cc;
        const float b0 = __ldg(&bias[col]), b1 = __ldg(&bias[col + 1]);
        #pragma unroll
        for (int i = 0; i < 2; i++) {
            const int r0 = bm * 128 + wm * 32 + i * 16 + cr;
            float2 v0 = {acc[i][j][0] + b0, acc[i][j][1] + b1};
            float2 v1 = {acc[i][j][2] + b0, acc[i][j][3] + b1};
            *(float2*)&C[(size_t)r0 * N + col]       = v0;
            *(float2*)&C[(size_t)(r0 + 8) * N + col] = v1;
        }
    }
}

// --------------------- persistent LSTM scan (one per layer) ----------------
// 128 CTAs x 256 thr. Inner product packed along k with fma.rn.f32x2:
// lane-lo accumulates even-k, lane-hi odd-k. hs stored [batch][k] so h pairs
// are contiguous; wres padded rows (H+4) for conflict-free float4 reads.
template <int H, int JR>
__global__ __launch_bounds__(256) void lstm_scan(
    const float* __restrict__ px,     // [T*32, 4H]
    const float* __restrict__ wh,     // [4H, H]
    const float* __restrict__ bh,     // [4H]
    const unsigned char* __restrict__ rm,
    float* __restrict__ hA, float* __restrict__ hB,
    float* __restrict__ c,
    float* __restrict__ y,            // [T*32, H]
    unsigned int* __restrict__ bar)
{
    constexpr int ROWS = 4 * JR;          // 40 or 16
    constexpr int TMr  = ROWS / 8;        // 5 or 2
    constexpr int KC   = H / 4;
    constexpr int NT   = KC / 32;
    constexpr int G    = 4 * H;
    constexpr int WRS  = H + 4;           // padded w row stride (floats)
    constexpr int HS_STR = 36, PS_STR = 33;
    constexpr int HS_BLK = 32 * HS_STR;   // per-kq h tile [b][k] (32x32 + pad)
    constexpr int PS_BLK = ROWS * PS_STR;
    constexpr int UNION_FL = (4 * HS_BLK > 4 * PS_BLK) ? 4 * HS_BLK : 4 * PS_BLK;
    constexpr int NE = (JR * 32 + 255) / 256;
    static_assert(ROWS % 8 == 0 && KC % 32 == 0, "tiling");

    extern __shared__ __align__(16) float smf[];
    float* wres = smf;                    // [ROWS][WRS]
    float* un   = smf + ROWS * WRS;       // hs (during tiles) / ps (after)
    float* c_s  = un + UNION_FL;          // [JR*32]

    const int tid = threadIdx.x;
    const int kq  = tid >> 6;             // K quarter
    const int f   = tid & 63;
    const int rg  = (tid >> 3) & 7;
    const int bq  = tid & 7;
    const int r0  = rg * TMr;
    const int j0  = blockIdx.x * JR;
    const unsigned ncta = gridDim.x;

    // ---- preload weights (coalesced gmem reads) + init c ----
    for (int idx = tid; idx < ROWS * H; idx += 256) {
        int lr = idx / H, k = idx - lr * H;
        int grow = (lr / JR) * H + j0 + (lr % JR);
        wres[lr * WRS + k] = wh[(size_t)grow * H + k];
    }
    for (int i = tid; i < JR * 32; i += 256) c_s[i] = 0.f;

    // ---- per-thread epilogue constants ----
    int ej[NE], eb[NE]; bool ev[NE]; float ebh[NE][4];
    #pragma unroll
    for (int n = 0; n < NE; n++) {
        int e = tid + n * 256;
        ev[n] = (e < JR * 32);
        ej[n] = e >> 5;
        eb[n] = e & 31;
        if (ev[n]) {
            #pragma unroll
            for (int g = 0; g < 4; g++)
                ebh[n][g] = bh[g * H + j0 + ej[n]];
        }
    }
    __syncthreads();

    for (int t = 0; t < T_LEN; t++) {
        const float* hin  = (t & 1) ? hB : hA;
        float*       hout = (t & 1) ? hA : hB;

        unsigned char rmS[4];
        #pragma unroll
        for (int i = 0; i < 4; i++) rmS[i] = rm[t * 32 + (f >> 3) + i * 8];

        // prefetch h tile 0
        float4 hv[4];
        #pragma unroll
        for (int i = 0; i < 4; i++) {
            int b = (f >> 3) + i * 8, k4 = f & 7;
            float4 v = __ldcg((const float4*)&hin[(size_t)b * H + kq * KC + k4 * 4]);
            if (rmS[i]) { v.x = 0.f; v.y = 0.f; v.z = 0.f; v.w = 0.f; }
            hv[i] = v;
        }

        // prefetch px (DRAM latency hidden behind the matvec)
        float pxv[NE][4]; unsigned char erm[NE];
        #pragma unroll
        for (int n = 0; n < NE; n++) {
            if (ev[n]) {
                erm[n] = rm[t * 32 + eb[n]];
                #pragma unroll
                for (int g = 0; g < 4; g++)
                    pxv[n][g] = __ldcg(&px[(size_t)(t * 32 + eb[n]) * G + g * H + j0 + ej[n]]);
            }
        }

        // packed accumulators: acc2[i][m] for row r0+i, batch bq+8m
        unsigned long long acc2[TMr][4];
        #pragma unroll
        for (int i = 0; i < TMr; i++)
            #pragma unroll
            for (int m = 0; m < 4; m++) acc2[i][m] = 0ull;

        for (int tile = 0; tile < NT; tile++) {
            __syncthreads();              // prev tile compute done
            #pragma unroll
            for (int i = 0; i < 4; i++) {
                int b = (f >> 3) + i * 8, k4 = f & 7;
                *(float4*)&un[kq * HS_BLK + b * HS_STR + k4 * 4] = hv[i];
            }
            __syncthreads();

            if (tile + 1 < NT) {          // prefetch next h tile
                const int k0 = kq * KC + (tile + 1) * 32;
                #pragma unroll
                for (int i = 0; i < 4; i++) {
                    int b = (f >> 3) + i * 8, k4 = f & 7;
                    float4 v = __ldcg((const float4*)&hin[(size_t)b * H + k0 + k4 * 4]);
                    if (rmS[i]) { v.x = 0.f; v.y = 0.f; v.z = 0.f; v.w = 0.f; }
                    hv[i] = v;
                }
            }

            const int kbase = kq * KC + tile * 32;
            #pragma unroll
            for (int k4 = 0; k4 < 8; k4++) {
                ulonglong2 wp[TMr];
                #pragma unroll
                for (int i = 0; i < TMr; i++)
                    wp[i] = *(const ulonglong2*)&wres[(r0 + i) * WRS + kbase + k4 * 4];
                ulonglong2 hp[4];
                #pragma unroll
                for (int m = 0; m < 4; m++)
                    hp[m] = *(const ulonglong2*)&un[kq * HS_BLK + (bq + 8 * m) * HS_STR + k4 * 4];
                #pragma unroll
                for (int i = 0; i < TMr; i++)
                    #pragma unroll
                    for (int m = 0; m < 4; m++) {
                        ffma2(acc2[i][m], wp[i].x, hp[m].x);
                        ffma2(acc2[i][m], wp[i].y, hp[m].y);
                    }
            }
        }

        __syncthreads();                  // hs dead -> reuse region as ps
        #pragma unroll
        for (int i = 0; i < TMr; i++)
            #pragma unroll
            for (int m = 0; m < 4; m++)
                un[kq * PS_BLK + (r0 + i) * PS_STR + bq + 8 * m] = unpack_sum(acc2[i][m]);
        __syncthreads();

        // ---- epilogue ----
        #pragma unroll
        for (int n = 0; n < NE; n++) {
            if (!ev[n]) continue;
            float pre[4];
            #pragma unroll
            for (int g = 0; g < 4; g++) {
                float s = ebh[n][g] + pxv[n][g];
                int r = g * JR + ej[n];
                #pragma unroll
                for (int q = 0; q < 4; q++)
                    s += un[q * PS_BLK + r * PS_STR + eb[n]];
                pre[g] = s;
            }
            float ig = 1.f / (1.f + __expf(-pre[0]));
            float fg = 1.f / (1.f + __expf(-pre[1]));
            float og = 1.f / (1.f + __expf(-pre[2]));
            float gg = 2.f / (1.f + __expf(-2.f * pre[3])) - 1.f;
            float cold = erm[n] ? 0.f : c_s[ej[n] * 32 + eb[n]];
            float cn = fg * cold + ig * gg;
            float th = 2.f / (1.f + __expf(-2.f * cn)) - 1.f;
            float hn = og * th;
            c_s[ej[n] * 32 + eb[n]] = cn;
            hout[(size_t)eb[n] * H + j0 + ej[n]] = hn;
            y[(size_t)(t * 32 + eb[n]) * H + j0 + ej[n]] = hn;
        }

        // ---- grid barrier ----
        if (t + 1 < T_LEN) {
            __threadfence();
            __syncthreads();
            if (tid == 0) {
                atomicAdd(bar, 1u);
                unsigned target = (unsigned)(t + 1) * ncta;
                while (*(volatile unsigned int*)bar < target) { }
            }
            __syncthreads();
        }
    }

    // flush c (needed only for last layer's c_last output)
    #pragma unroll
    for (int n = 0; n < NE; n++)
        if (ev[n])
            c[(size_t)eb[n] * H + j0 + ej[n]] = c_s[ej[n] * 32 + eb[n]];
}

// ------------------------------- launch -------------------------------------
extern "C" void kernel_launch(void* const* d_in, const int* in_sizes, int n_in,
                              void* d_out, int out_size)
{
    (void)in_sizes; (void)n_in; (void)out_size;
    const float* x   = (const float*)d_in[0];
    const int*   tok = (const int*)d_in[1];
    const float* wi[3] = {(const float*)d_in[2], (const float*)d_in[6],  (const float*)d_in[10]};
    const float* bi[3] = {(const float*)d_in[3], (const float*)d_in[7],  (const float*)d_in[11]};
    const float* wh[3] = {(const float*)d_in[4], (const float*)d_in[8],  (const float*)d_in[12]};
    const float* bh[3] = {(const float*)d_in[5], (const float*)d_in[9],  (const float*)d_in[13]};
    float* out = (float*)d_out;

    float *px = nullptr, *y0 = nullptr, *y1 = nullptr, *hA = nullptr,
          *hB = nullptr, *cb = nullptr;
    unsigned char* rmp = nullptr;
    unsigned int* bar = nullptr;
    __nv_bfloat16 *ahi = nullptr, *alo = nullptr, *bhi = nullptr, *blo = nullptr;
    cudaGetSymbolAddress((void**)&px,  g_px);
    cudaGetSymbolAddress((void**)&y0,  g_y0);
    cudaGetSymbolAddress((void**)&y1,  g_y1);
    cudaGetSymbolAddress((void**)&hA,  g_hA);
    cudaGetSymbolAddress((void**)&hB,  g_hB);
    cudaGetSymbolAddress((void**)&cb,  g_c);
    cudaGetSymbolAddress((void**)&rmp, g_rm);
    cudaGetSymbolAddress((void**)&bar, g_bar);
    cudaGetSymbolAddress((void**)&ahi, g_ahi);
    cudaGetSymbolAddress((void**)&alo, g_alo);
    cudaGetSymbolAddress((void**)&bhi, g_bhi);
    cudaGetSymbolAddress((void**)&blo, g_blo);

    cudaFuncSetAttribute(tc_gemm, cudaFuncAttributeMaxDynamicSharedMemorySize,
                         TC_SMEM);
    // scan smem: l0/l1: (40*1284 + 5280 + 320)*4 = 227840 B
    //            l2:    (16*516  + 4608 + 128)*4 = 51968 B
    const int SCAN_SMEM_BIG   = (40 * (HHID + 4) + 5280 + 320) * 4;
    const int SCAN_SMEM_SMALL = (16 * (DIN + 4) + 4608 + 128) * 4;
    cudaFuncSetAttribute(lstm_scan<HHID, 10>,
                         cudaFuncAttributeMaxDynamicSharedMemorySize, SCAN_SMEM_BIG);
    cudaFuncSetAttribute(lstm_scan<DIN, 4>,
                         cudaFuncAttributeMaxDynamicSharedMemorySize, SCAN_SMEM_SMALL);

    setup_rm<<<64, 256>>>(tok, rmp);

    const float* lin[3] = {x, y0, y1};
    float*       lys[3] = {y0, y1, out};
    const int Hs[3] = {HHID, HHID, DIN};
    const int Ks[3] = {DIN, HHID, HHID};

    for (int l = 0; l < 3; l++) {
        const int H = Hs[l], G = 4 * H, K = Ks[l];
        const int n = BATCH * H;
        init_layer<<<(n + 255) / 256, 256>>>(hA, hB, bar, n);

        const int na4 = (16384 * K) / 4;
        const int nb4 = (G * K) / 4;
        cvt_split<<<(na4 + 255) / 256, 256>>>(lin[l], ahi, alo, na4);
        cvt_split<<<(nb4 + 255) / 256, 256>>>(wi[l], bhi, blo, nb4);

        tc_gemm<<<dim3(G / 128, 16384 / 128), 256, TC_SMEM>>>(
            ahi, alo, bhi, blo, bi[l], px, K, G);

        if (l < 2) {
            lstm_scan<HHID, 10><<<128, 256, SCAN_SMEM_BIG>>>(
                px, wh[l], bh[l], rmp, hA, hB, cb, lys[l], bar);
        } else {
            lstm_scan<DIN, 4><<<128, 256, SCAN_SMEM_SMALL>>>(
                px, wh[l], bh[l], rmp, hA, hB, cb, lys[l], bar);
        }
    }

    // T_LEN even -> final h lives in hA; append h_last, c_last after y2
    cudaMemcpyAsync(out + 8388608,         hA, BATCH * DIN * sizeof(float),
                    cudaMemcpyDeviceToDevice);
    cudaMemcpyAsync(out + 8388608 + 16384, cb, BATCH * DIN * sizeof(float),
                    cudaMemcpyDeviceToDevice);
}